// round 7
// baseline (speedup 1.0000x reference)
#include <cuda_runtime.h>

// SGDW: out = p * (1 - LR*WD) - LR * (MOM * v + g)
// LR=0.01, MOM=0.9, WD=0.0001
//
// 256-bit (v8.f32) global loads/stores — Blackwell sm_100+ feature.
// 128 threads/block, 1 float8/thread => 1024 floats per block. Every tensor
// is an exact multiple of 1024 elements, so each block lies entirely inside
// one segment (uniform per-block select) and the grid divides exactly.

#define LR    0.01f
#define MOM   0.9f
#define DECAY (1.0f - 0.01f * 0.0001f)

struct f8 { float v[8]; };

__device__ __forceinline__ f8 ldg256(const float* p) {
    f8 r;
    asm("ld.global.nc.v8.f32 {%0,%1,%2,%3,%4,%5,%6,%7}, [%8];"
        : "=f"(r.v[0]), "=f"(r.v[1]), "=f"(r.v[2]), "=f"(r.v[3]),
          "=f"(r.v[4]), "=f"(r.v[5]), "=f"(r.v[6]), "=f"(r.v[7])
        : "l"(p));
    return r;
}

__device__ __forceinline__ void stg256(float* p, const f8& r) {
    asm volatile("st.global.v8.f32 [%0], {%1,%2,%3,%4,%5,%6,%7,%8};"
        :: "l"(p),
           "f"(r.v[0]), "f"(r.v[1]), "f"(r.v[2]), "f"(r.v[3]),
           "f"(r.v[4]), "f"(r.v[5]), "f"(r.v[6]), "f"(r.v[7])
        : "memory");
}

__global__ void __launch_bounds__(128)
sgdw_fused(const float* __restrict__ p0, const float* __restrict__ g0, const float* __restrict__ v0,
           const float* __restrict__ p1, const float* __restrict__ g1, const float* __restrict__ v1,
           const float* __restrict__ p2, const float* __restrict__ g2, const float* __restrict__ v2,
           const float* __restrict__ p3, const float* __restrict__ g3, const float* __restrict__ v3,
           float* __restrict__ out,
           int boff1, int boff2, int boff3)   // segment boundaries in BLOCKS (1024 floats each)
{
    int b = blockIdx.x;
    long long base = (long long)b * 1024 + threadIdx.x * 8;   // float index in out

    // Uniform per-block segment select — zero per-thread divergence.
    const float *p, *g, *v;
    long long j;
    if (b < boff1)      { p = p0; g = g0; v = v0; j = base; }
    else if (b < boff2) { p = p1; g = g1; v = v1; j = base - (long long)boff1 * 1024; }
    else if (b < boff3) { p = p2; g = g2; v = v2; j = base - (long long)boff2 * 1024; }
    else                { p = p3; g = g3; v = v3; j = base - (long long)boff3 * 1024; }

    f8 pv = ldg256(p + j);
    f8 gv = ldg256(g + j);
    f8 vv = ldg256(v + j);

    f8 o;
#pragma unroll
    for (int k = 0; k < 8; k++)
        o.v[k] = fmaf(pv.v[k], DECAY, -LR * fmaf(MOM, vv.v[k], gv.v[k]));

    stg256(out + base, o);
}

extern "C" void kernel_launch(void* const* d_in, const int* in_sizes, int n_in,
                              void* d_out, int out_size)
{
    // setup_inputs() inserts p{i}, g{i}, v{i} per tensor -> interleaved order.
    bool il = (in_sizes[0] == in_sizes[1]) && (in_sizes[1] == in_sizes[2]);

    const float* P[4]; const float* G[4]; const float* V[4];
    int boff[5];               // cumulative block counts (1024 floats per block)
    boff[0] = 0;
    for (int t = 0; t < 4; t++) {
        int n;
        if (il) {
            P[t] = (const float*)d_in[3 * t + 0];
            G[t] = (const float*)d_in[3 * t + 1];
            V[t] = (const float*)d_in[3 * t + 2];
            n = in_sizes[3 * t];
        } else {
            P[t] = (const float*)d_in[t];
            G[t] = (const float*)d_in[4 + t];
            V[t] = (const float*)d_in[8 + t];
            n = in_sizes[t];
        }
        boff[t + 1] = boff[t] + n / 1024;   // exact division for all tensors
    }
    int blocks = boff[4];

    sgdw_fused<<<blocks, 128>>>(P[0], G[0], V[0],
                                P[1], G[1], V[1],
                                P[2], G[2], V[2],
                                P[3], G[3], V[3],
                                (float*)d_out,
                                boff[1], boff[2], boff[3]);
}